// round 6
// baseline (speedup 1.0000x reference)
#include <cuda_runtime.h>
#include <cuda_fp16.h>
#include <math.h>
#include <stdint.h>

#define BB   16
#define CH   64
#define HH   256
#define WW   256
#define NIMG (BB*CH)        // 1024
#define NPX  (BB*HH*WW)     // 1048576 flat pixels

// ---------------- scratch (static __device__ allocations only) ----------------
__device__ __align__(16) float g_X1 [NIMG*HH*32];
__device__ __align__(16) float g_CFT[NIMG*512*2];
__device__ __align__(16) float g_OFT[NIMG*512*2];
__device__ __align__(16) float g_G  [NIMG*HH*WW];
__device__ __align__(16) float g_tabA [256*32];
__device__ __align__(16) float g_tabFT[32*256];
__device__ __align__(16) float g_cosT[256];
__device__ __align__(16) float g_sinT[256];
__device__ __align__(16) float g_wT [CH*9*CH];          // [ci][tap][co] (patch kernel)
__device__ __align__(16) __half g_cThi[(size_t)NPX*64]; // [px][ci] fp16 hi
__device__ __align__(16) __half g_cTlo[(size_t)NPX*64]; // [px][ci] fp16 lo
__device__ __align__(1024) char g_wPk[18*8192];         // [tap][hi/lo] 64x64 f16 swizzled

// ---------------- helpers ----------------
__device__ __forceinline__ uint32_t smem_u32(const void* p) {
    return (uint32_t)__cvta_generic_to_shared(p);
}
#define SWZ128(bo) ((bo) ^ (((bo) >> 3) & 0x70))

__device__ __forceinline__ void cpasync16(uint32_t saddr, const void* gptr) {
    asm volatile("cp.async.cg.shared.global [%0], [%1], 16;"
                 :: "r"(saddr), "l"(__cvta_generic_to_global(gptr)) : "memory");
}
#define CP_COMMIT()  asm volatile("cp.async.commit_group;" ::: "memory")
#define CP_WAIT0()   asm volatile("cp.async.wait_group 0;" ::: "memory")
#define CP_WAIT1()   asm volatile("cp.async.wait_group 1;" ::: "memory")

__device__ __forceinline__ void ldsm4(uint32_t* r, uint32_t addr) {
    asm volatile("ldmatrix.sync.aligned.m8n8.x4.shared.b16 {%0,%1,%2,%3}, [%4];"
                 : "=r"(r[0]), "=r"(r[1]), "=r"(r[2]), "=r"(r[3]) : "r"(addr));
}
__device__ __forceinline__ void mma16816(float* c, const uint32_t* a, const uint32_t* b) {
    asm volatile(
        "mma.sync.aligned.m16n8k16.row.col.f32.f16.f16.f32 "
        "{%0,%1,%2,%3}, {%4,%5,%6,%7}, {%8,%9}, {%0,%1,%2,%3};"
        : "+f"(c[0]), "+f"(c[1]), "+f"(c[2]), "+f"(c[3])
        : "r"(a[0]), "r"(a[1]), "r"(a[2]), "r"(a[3]), "r"(b[0]), "r"(b[1]));
}

// ---------------- init ----------------
__global__ void k_init(const float* __restrict__ conv_w) {
    const float TWO_PI = 6.28318530717958647692f;
    int tid = blockIdx.x * blockDim.x + threadIdx.x;
    int stride = gridDim.x * blockDim.x;

    if (tid < 256) {
        float ang = TWO_PI * (float)tid / 256.0f;
        g_cosT[tid] = cosf(ang);
        g_sinT[tid] = sinf(ang);
    }
    for (int idx = tid; idx < 256*32; idx += stride) {
        int x = idx >> 5, n = idx & 31, kx = n >> 1;
        float ang = TWO_PI * (float)((kx * x) & 255) / 256.0f;
        g_tabA[idx] = (n & 1) ? -sinf(ang) : cosf(ang);
    }
    for (int idx = tid; idx < 32*256; idx += stride) {
        int n = idx >> 8, x = idx & 255, kx = n >> 1;
        float sc = (kx == 0 ? 1.0f : 2.0f) / 65536.0f;
        float ang = TWO_PI * (float)((kx * x) & 255) / 256.0f;
        g_tabFT[idx] = (n & 1) ? -sc * sinf(ang) : sc * cosf(ang);
    }
    for (int idx = tid; idx < CH*9*CH; idx += stride) {
        int co = idx & 63;
        int rest = idx >> 6;
        int t  = rest % 9;
        int ci = rest / 9;
        g_wT[idx] = conv_w[(co*CH + ci)*9 + t];
    }
    // packed f16 hi/lo weights [tap][hl][co rows][ci], 128B rows, XOR-swizzled
    for (int idx = tid; idx < 9*4096; idx += stride) {
        int t = idx >> 12;
        int r = idx & 4095;
        int co = r >> 6, ci = r & 63;
        float w = conv_w[(co*CH + ci)*9 + t];
        __half hi = __float2half_rn(w);
        __half lo = __float2half_rn(w - __half2float(hi));
        uint32_t boff = SWZ128((uint32_t)(co*128 + ci*2));
        *(__half*)(g_wPk + (size_t)(t*2+0)*8192 + boff) = hi;
        *(__half*)(g_wPk + (size_t)(t*2+1)*8192 + boff) = lo;
    }
}

// ---------------- kT: transpose input -> [px][ci] f16 hi/lo ----------------
__global__ void __launch_bounds__(256) kT(const float* __restrict__ c) {
    __shared__ float ts[64][65];
    int tid = threadIdx.x;
    int xc = blockIdx.x * 64;
    int y  = blockIdx.y;
    int b  = blockIdx.z;
    #pragma unroll
    for (int j = 0; j < 16; j++) {
        int idx = tid + j*256;
        int ci = idx >> 6, xx = idx & 63;
        ts[ci][xx] = c[((size_t)(b*64 + ci))*65536 + y*256 + xc + xx];
    }
    __syncthreads();
    size_t pxbase = (((size_t)b*256 + y)*256 + xc);
    #pragma unroll
    for (int j = 0; j < 16; j++) {
        int idx = tid + j*256;
        int xx = idx >> 6, ci = idx & 63;
        float v = ts[ci][xx];
        __half hi = __float2half_rn(v);
        __half lo = __float2half_rn(v - __half2float(hi));
        g_cThi[(pxbase + xx)*64 + ci] = hi;
        g_cTlo[(pxbase + xx)*64 + ci] = lo;
    }
}

// ---------------- Kernel A ----------------
__global__ void __launch_bounds__(256) kA(const float* __restrict__ c) {
    __shared__ float tab[8192];
    __shared__ float rows[8][256];
    int tid = threadIdx.x;
    for (int i = tid; i < 8192; i += 256) tab[i] = g_tabA[i];
    __syncthreads();
    int w = tid >> 5, lane = tid & 31;
    int rowBase = blockIdx.x * 128;
    for (int it = 0; it < 16; it++) {
        int row = rowBase + it*8 + w;
        const float* src = c + (size_t)row * 256;
        #pragma unroll
        for (int k = 0; k < 8; k++) rows[w][lane + k*32] = src[lane + k*32];
        __syncwarp();
        float a0 = 0.f, a1 = 0.f, a2 = 0.f, a3 = 0.f;
        #pragma unroll 4
        for (int x = 0; x < 256; x += 4) {
            a0 += rows[w][x+0] * tab[(x+0)*32 + lane];
            a1 += rows[w][x+1] * tab[(x+1)*32 + lane];
            a2 += rows[w][x+2] * tab[(x+2)*32 + lane];
            a3 += rows[w][x+3] * tab[(x+3)*32 + lane];
        }
        g_X1[(size_t)row*32 + lane] = (a0 + a1) + (a2 + a3);
        __syncwarp();
    }
}

// ---------------- Kernel B ----------------
__global__ void __launch_bounds__(512) kB() {
    __shared__ float xs[8192];
    __shared__ float csm[256], ssm[256];
    int tid = threadIdx.x;
    int img = blockIdx.x;
    const float* src = g_X1 + (size_t)img * 8192;
    for (int i = tid; i < 8192; i += 512) xs[i] = src[i];
    if (tid < 256) { csm[tid] = g_cosT[tid]; ssm[tid] = g_sinT[tid]; }
    __syncthreads();
    int kyi = tid >> 4, kx = tid & 15;
    int ky = (kyi < 16) ? kyi : kyi + 224;
    float ar = 0.f, ai = 0.f;
    for (int y = 0; y < 256; y++) {
        int j = (ky * y) & 255;
        float cv = csm[j], sv = ssm[j];
        float2 v = *(const float2*)&xs[y*32 + 2*kx];
        ar += v.x * cv + v.y * sv;
        ai += v.y * cv - v.x * sv;
    }
    *(float2*)&g_CFT[((size_t)img*512 + tid)*2] = make_float2(ar, ai);
}

// ---------------- Kernel C ----------------
__global__ void __launch_bounds__(128) kC(const float* __restrict__ w1r, const float* __restrict__ w1i,
                                          const float* __restrict__ w2r, const float* __restrict__ w2i) {
    __shared__ float wr_s[4096], wi_s[4096], cf_s[2048];
    int tid = threadIdx.x;
    int m = blockIdx.x;
    int kyi = m >> 4, kx = m & 15;
    const float* br; const float* bi; int woff;
    if (kyi < 16) { br = w1r; bi = w1i; woff = kyi*16 + kx; }
    else          { br = w2r; bi = w2i; woff = (kyi-16)*16 + kx; }
    for (int idx = tid; idx < 4096; idx += 128) {
        wr_s[idx] = br[idx*256 + woff];
        wi_s[idx] = bi[idx*256 + woff];
    }
    for (int idx = tid; idx < 1024; idx += 128) {
        float2 v = *(const float2*)&g_CFT[((size_t)idx*512 + m)*2];
        cf_s[2*idx] = v.x; cf_s[2*idx+1] = v.y;
    }
    __syncthreads();
    int o = tid & 63, h = tid >> 6;
    float aR[8], aI[8];
    #pragma unroll
    for (int q = 0; q < 8; q++) { aR[q] = 0.f; aI[q] = 0.f; }
    for (int i = 0; i < 64; i++) {
        float wr = wr_s[i*64 + o], wi = wi_s[i*64 + o];
        #pragma unroll
        for (int q = 0; q < 8; q++) {
            int b = h*8 + q;
            float cr = cf_s[(b*64 + i)*2], ci2 = cf_s[(b*64 + i)*2 + 1];
            aR[q] += cr*wr - ci2*wi;
            aI[q] += cr*wi + ci2*wr;
        }
    }
    #pragma unroll
    for (int q = 0; q < 8; q++) {
        int b = h*8 + q;
        *(float2*)&g_OFT[(((size_t)b*64 + o)*512 + m)*2] = make_float2(aR[q], aI[q]);
    }
}

// ---------------- Kernel D ----------------
__global__ void __launch_bounds__(256) kD() {
    __shared__ float tmp[256*34];
    __shared__ float oft_s[1024];
    __shared__ float csm[256], ssm[256];
    int tid = threadIdx.x;
    int img = blockIdx.x;
    const float* src = g_OFT + (size_t)img * 1024;
    for (int i = tid; i < 1024; i += 256) oft_s[i] = src[i];
    if (tid < 256) { csm[tid] = g_cosT[tid]; ssm[tid] = g_sinT[tid]; }
    __syncthreads();
    {
        int y = tid;
        float aR[16], aI[16];
        #pragma unroll
        for (int k = 0; k < 16; k++) { aR[k] = 0.f; aI[k] = 0.f; }
        for (int kyi = 0; kyi < 32; kyi++) {
            int ky = (kyi < 16) ? kyi : kyi + 224;
            int j = (ky * y) & 255;
            float cv = csm[j], sv = ssm[j];
            const float* ob = &oft_s[kyi*32];
            #pragma unroll
            for (int kx = 0; kx < 16; kx++) {
                float orr = ob[2*kx], oii = ob[2*kx+1];
                aR[kx] += orr*cv - oii*sv;
                aI[kx] += orr*sv + oii*cv;
            }
        }
        #pragma unroll
        for (int kx = 0; kx < 16; kx++) {
            tmp[y*34 + 2*kx]   = aR[kx];
            tmp[y*34 + 2*kx+1] = aI[kx];
        }
    }
    __syncthreads();
    {
        int x = tid;
        float f[32];
        #pragma unroll
        for (int n = 0; n < 32; n++) f[n] = g_tabFT[n*256 + x];
        float* gdst = g_G + (size_t)img * 65536;
        for (int y = 0; y < 256; y++) {
            const float* tr = &tmp[y*34];
            float a0 = 0.f, a1 = 0.f, a2 = 0.f, a3 = 0.f;
            #pragma unroll
            for (int n = 0; n < 32; n += 4) {
                a0 += tr[n+0] * f[n+0];
                a1 += tr[n+1] * f[n+1];
                a2 += tr[n+2] * f[n+2];
                a3 += tr[n+3] * f[n+3];
            }
            gdst[y*256 + x] = (a0 + a1) + (a2 + a3);
        }
    }
}

// ---------------- kE3: mma.sync f16-split conv * G -> out ----------------
// SMEM layout: [0,256) bias | [1024, 148480) W (18 x 8KB) | [148480, 214016) A 2 bufs
#define E3_SM_W   1024
#define E3_SM_A   148480
#define E3_SMEM   214016
#define E3_NT     4

__device__ __forceinline__ void stageA(uint32_t dst, long long px0, int tap, int tid) {
    int dy = tap / 3, dx = tap - dy * 3;
    long long off = (long long)(dy - 1) * 256 + (dx - 1);
    #pragma unroll
    for (int j = 0; j < 8; j++) {
        int o = tid + j * 128;
        int row = o >> 3, ch = o & 7;
        long long spx = px0 + row + off;
        spx = spx < 0 ? 0 : (spx >= NPX ? (long long)(NPX - 1) : spx);
        uint32_t d = SWZ128((uint32_t)(row * 128 + ch * 16));
        cpasync16(dst + d,         g_cThi + spx * 64 + ch * 8);
        cpasync16(dst + 16384 + d, g_cTlo + spx * 64 + ch * 8);
    }
}

__global__ void __launch_bounds__(128, 1) kE3(const float* __restrict__ bias,
                                              float* __restrict__ out) {
    extern __shared__ char sm[];
    uint32_t smb = smem_u32(sm);
    int tid = threadIdx.x, w = tid >> 5, lane = tid & 31;

    if (tid < 64) ((float*)sm)[tid] = bias[tid];
    for (int i = tid; i < 9216; i += 128)
        cpasync16(smb + E3_SM_W + i * 16, (const char*)g_wPk + (size_t)i * 16);
    CP_COMMIT();                                   // group: W

    // lane constants for ldmatrix addressing
    int arow0 = w * 32 + (lane & 15);              // + mb*16
    int a_uh  = lane >> 4;                         // A 16B-col half
    int wrow  = (lane & 7) + ((lane >> 4) << 3);   // + np*16
    int w_uh  = (lane >> 3) & 1;                   // W 16B-col half
    int erow  = lane >> 2;                         // epilogue row in m16 block
    int ecol  = (lane & 3) * 2;                    // epilogue n within n8 block

    long long px0_base = (long long)blockIdx.x * (E3_NT * 128);

    float acc[2][8][4];

    stageA(smb + E3_SM_A, px0_base, 0, tid);       // tile0 tap0 -> buf0
    CP_COMMIT();

    const int T = E3_NT * 9;
    for (int t = 0; t < T; t++) {
        int tile = t / 9, tap = t - tile * 9;
        int buf = t & 1;
        if (t + 1 < T) {
            int t2 = t + 1, tile2 = t2 / 9, tap2 = t2 - tile2 * 9;
            stageA(smb + E3_SM_A + (t2 & 1) * 32768,
                   px0_base + (long long)tile2 * 128, tap2, tid);
            CP_COMMIT();
            CP_WAIT1();
        } else {
            CP_WAIT0();
        }
        __syncthreads();

        if (tap == 0) {
            #pragma unroll
            for (int mb = 0; mb < 2; mb++)
                #pragma unroll
                for (int nb = 0; nb < 8; nb++)
                    #pragma unroll
                    for (int q = 0; q < 4; q++) acc[mb][nb][q] = 0.f;
        }

        uint32_t Ab = smb + E3_SM_A + buf * 32768;
        uint32_t Wb = smb + E3_SM_W + tap * 16384;
        #pragma unroll
        for (int kc = 0; kc < 4; kc++) {
            uint32_t ah[2][4], al[2][4], wf[4][4];
            uint32_t wad[4];
            #pragma unroll
            for (int mb = 0; mb < 2; mb++) {
                int row = arow0 + mb * 16;
                uint32_t ra = Ab + row * 128 + (((kc * 2 + a_uh) ^ (row & 7)) << 4);
                ldsm4(ah[mb], ra);
                ldsm4(al[mb], ra + 16384);
            }
            #pragma unroll
            for (int np = 0; np < 4; np++) {
                int row = np * 16 + wrow;
                wad[np] = Wb + row * 128 + (((kc * 2 + w_uh) ^ (row & 7)) << 4);
                ldsm4(wf[np], wad[np]);            // W hi
            }
            #pragma unroll
            for (int mb = 0; mb < 2; mb++)
                #pragma unroll
                for (int nb = 0; nb < 8; nb++)
                    mma16816(acc[mb][nb], ah[mb], &wf[nb >> 1][(nb & 1) * 2]);
            #pragma unroll
            for (int mb = 0; mb < 2; mb++)
                #pragma unroll
                for (int nb = 0; nb < 8; nb++)
                    mma16816(acc[mb][nb], al[mb], &wf[nb >> 1][(nb & 1) * 2]);
            #pragma unroll
            for (int np = 0; np < 4; np++)
                ldsm4(wf[np], wad[np] + 8192);     // W lo (reuse regs)
            #pragma unroll
            for (int mb = 0; mb < 2; mb++)
                #pragma unroll
                for (int nb = 0; nb < 8; nb++)
                    mma16816(acc[mb][nb], ah[mb], &wf[nb >> 1][(nb & 1) * 2]);
        }
        __syncthreads();

        if (tap == 8) {
            // epilogue: bias + global-branch multiply
            const float* bias_s = (const float*)sm;
            long long pxw = px0_base + (long long)tile * 128 + w * 32 + erow;
            #pragma unroll
            for (int mb = 0; mb < 2; mb++) {
                long long pxA = pxw + mb * 16;
                long long pxB = pxA + 8;
                size_t baseA = ((size_t)(pxA >> 16)) * 64 * 65536 + (size_t)(pxA & 65535);
                size_t baseB = ((size_t)(pxB >> 16)) * 64 * 65536 + (size_t)(pxB & 65535);
                #pragma unroll
                for (int nb = 0; nb < 8; nb++) {
                    int co = nb * 8 + ecol;
                    float b0 = bias_s[co], b1 = bias_s[co + 1];
                    size_t i00 = baseA + (size_t)co * 65536;
                    size_t i01 = i00 + 65536;
                    size_t i10 = baseB + (size_t)co * 65536;
                    size_t i11 = i10 + 65536;
                    out[i00] = (acc[mb][nb][0] + b0) * g_G[i00];
                    out[i01] = (acc[mb][nb][1] + b1) * g_G[i01];
                    out[i10] = (acc[mb][nb][2] + b0) * g_G[i10];
                    out[i11] = (acc[mb][nb][3] + b1) * g_G[i11];
                }
            }
        }
    }
}

// ---------------- kP: exact fp32 patch of wrap-border pixels ----------------
__global__ void __launch_bounds__(256) kP(const float* __restrict__ c,
                                          const float* __restrict__ bias,
                                          float* __restrict__ out) {
    int b = blockIdx.x;
    int s = blockIdx.y;
    int cobase = blockIdx.z * 16;
    int t = threadIdx.x;
    int y, x;
    if (s == 0)      { y = 0;   x = t; }
    else if (s == 1) { y = 255; x = t; }
    else if (s == 2) { y = t;   x = 0; }
    else             { y = t;   x = 255; }

    float acc[16];
    #pragma unroll
    for (int q = 0; q < 16; q++) acc[q] = 0.f;

    const float* cb = c + (size_t)b * 64 * 65536;
    for (int ci = 0; ci < 64; ci++) {
        const float* p = cb + (size_t)ci * 65536;
        float v[9];
        #pragma unroll
        for (int dy = 0; dy < 3; dy++)
            #pragma unroll
            for (int dx = 0; dx < 3; dx++)
                v[dy*3+dx] = p[((y + dy + 255) & 255) * 256 + ((x + dx + 255) & 255)];
        #pragma unroll
        for (int tap = 0; tap < 9; tap++) {
            const float* wrow = g_wT + ci*576 + tap*64 + cobase;
            #pragma unroll
            for (int q = 0; q < 16; q++) acc[q] += v[tap] * __ldg(&wrow[q]);
        }
    }
    size_t base = (size_t)b * 64 * 65536 + (size_t)y * 256 + x;
    #pragma unroll
    for (int q = 0; q < 16; q++) {
        int co = cobase + q;
        size_t idx = base + (size_t)co * 65536;
        out[idx] = (acc[q] + bias[co]) * g_G[idx];
    }
}

// ---------------- launch ----------------
extern "C" void kernel_launch(void* const* d_in, const int* in_sizes, int n_in,
                              void* d_out, int out_size) {
    const float* c      = (const float*)d_in[0];
    const float* w1r    = (const float*)d_in[1];
    const float* w1i    = (const float*)d_in[2];
    const float* w2r    = (const float*)d_in[3];
    const float* w2i    = (const float*)d_in[4];
    const float* conv_w = (const float*)d_in[5];
    const float* conv_b = (const float*)d_in[6];
    float* out = (float*)d_out;

    cudaFuncSetAttribute(kE3, cudaFuncAttributeMaxDynamicSharedMemorySize, E3_SMEM);

    k_init<<<64, 256>>>(conv_w);
    kT<<<dim3(4, 256, 16), 256>>>(c);
    kA<<<2048, 256>>>(c);
    kB<<<1024, 512>>>();
    kC<<<512, 128>>>(w1r, w1i, w2r, w2i);
    kD<<<1024, 256>>>();
    kE3<<<2048, 128, E3_SMEM>>>(conv_b, out);
    kP<<<dim3(16, 4, 4), 256>>>(c, conv_b, out);
}

// round 7
// speedup vs baseline: 1.4014x; 1.4014x over previous
#include <cuda_runtime.h>
#include <cuda_fp16.h>
#include <math.h>
#include <stdint.h>

#define BB   16
#define CH   64
#define HH   256
#define WW   256
#define NIMG (BB*CH)        // 1024
#define NPX  (BB*HH*WW)     // 1048576 flat pixels

// ---------------- scratch (static __device__ allocations only) ----------------
__device__ __align__(16) float g_X1 [NIMG*HH*32];
__device__ __align__(16) float g_CFT[NIMG*512*2];
__device__ __align__(16) float g_OFT[NIMG*512*2];
__device__ __align__(16) float g_G  [NIMG*HH*WW];
__device__ __align__(16) float g_tabA [256*32];
__device__ __align__(16) float g_tabFT[32*256];
__device__ __align__(16) float g_cosT[256];
__device__ __align__(16) float g_sinT[256];
__device__ __align__(16) float g_wT [CH*9*CH];          // [ci][tap][co] (patch kernel)
__device__ __align__(16) __half g_cThi[(size_t)NPX*64]; // [px][ci] fp16 hi
__device__ __align__(16) __half g_cTlo[(size_t)NPX*64]; // [px][ci] fp16 lo
__device__ __align__(1024) char g_wPk[18*8192];         // [tap][hi/lo] 64x64 f16 swizzled

// ---------------- helpers ----------------
__device__ __forceinline__ uint32_t smem_u32(const void* p) {
    return (uint32_t)__cvta_generic_to_shared(p);
}
#define SWZ128(bo) ((bo) ^ (((bo) >> 3) & 0x70))

__device__ __forceinline__ void cpasync16(uint32_t saddr, const void* gptr) {
    asm volatile("cp.async.cg.shared.global [%0], [%1], 16;"
                 :: "r"(saddr), "l"(__cvta_generic_to_global(gptr)) : "memory");
}
#define CP_COMMIT()  asm volatile("cp.async.commit_group;" ::: "memory")
#define CP_WAIT0()   asm volatile("cp.async.wait_group 0;" ::: "memory")
#define CP_WAIT1()   asm volatile("cp.async.wait_group 1;" ::: "memory")

__device__ __forceinline__ void ldsm4(uint32_t* r, uint32_t addr) {
    asm volatile("ldmatrix.sync.aligned.m8n8.x4.shared.b16 {%0,%1,%2,%3}, [%4];"
                 : "=r"(r[0]), "=r"(r[1]), "=r"(r[2]), "=r"(r[3]) : "r"(addr));
}
__device__ __forceinline__ void mma16816(float* c, const uint32_t* a, const uint32_t* b) {
    asm volatile(
        "mma.sync.aligned.m16n8k16.row.col.f32.f16.f16.f32 "
        "{%0,%1,%2,%3}, {%4,%5,%6,%7}, {%8,%9}, {%0,%1,%2,%3};"
        : "+f"(c[0]), "+f"(c[1]), "+f"(c[2]), "+f"(c[3])
        : "r"(a[0]), "r"(a[1]), "r"(a[2]), "r"(a[3]), "r"(b[0]), "r"(b[1]));
}

// ---------------- init ----------------
__global__ void k_init(const float* __restrict__ conv_w) {
    const float TWO_PI = 6.28318530717958647692f;
    int tid = blockIdx.x * blockDim.x + threadIdx.x;
    int stride = gridDim.x * blockDim.x;

    if (tid < 256) {
        float ang = TWO_PI * (float)tid / 256.0f;
        g_cosT[tid] = cosf(ang);
        g_sinT[tid] = sinf(ang);
    }
    for (int idx = tid; idx < 256*32; idx += stride) {
        int x = idx >> 5, n = idx & 31, kx = n >> 1;
        float ang = TWO_PI * (float)((kx * x) & 255) / 256.0f;
        g_tabA[idx] = (n & 1) ? -sinf(ang) : cosf(ang);
    }
    for (int idx = tid; idx < 32*256; idx += stride) {
        int n = idx >> 8, x = idx & 255, kx = n >> 1;
        float sc = (kx == 0 ? 1.0f : 2.0f) / 65536.0f;
        float ang = TWO_PI * (float)((kx * x) & 255) / 256.0f;
        g_tabFT[idx] = (n & 1) ? -sc * sinf(ang) : sc * cosf(ang);
    }
    for (int idx = tid; idx < CH*9*CH; idx += stride) {
        int co = idx & 63;
        int rest = idx >> 6;
        int t  = rest % 9;
        int ci = rest / 9;
        g_wT[idx] = conv_w[(co*CH + ci)*9 + t];
    }
    // packed f16 hi/lo weights [tap][hl][co rows][ci], 128B rows, XOR-swizzled
    for (int idx = tid; idx < 9*4096; idx += stride) {
        int t = idx >> 12;
        int r = idx & 4095;
        int co = r >> 6, ci = r & 63;
        float w = conv_w[(co*CH + ci)*9 + t];
        __half hi = __float2half_rn(w);
        __half lo = __float2half_rn(w - __half2float(hi));
        uint32_t boff = SWZ128((uint32_t)(co*128 + ci*2));
        *(__half*)(g_wPk + (size_t)(t*2+0)*8192 + boff) = hi;
        *(__half*)(g_wPk + (size_t)(t*2+1)*8192 + boff) = lo;
    }
}

// ---------------- kT: transpose input -> [px][ci] f16 hi/lo ----------------
__global__ void __launch_bounds__(256) kT(const float* __restrict__ c) {
    __shared__ float ts[64][65];
    int tid = threadIdx.x;
    int xc = blockIdx.x * 64;
    int y  = blockIdx.y;
    int b  = blockIdx.z;
    #pragma unroll
    for (int j = 0; j < 16; j++) {
        int idx = tid + j*256;
        int ci = idx >> 6, xx = idx & 63;
        ts[ci][xx] = c[((size_t)(b*64 + ci))*65536 + y*256 + xc + xx];
    }
    __syncthreads();
    size_t pxbase = (((size_t)b*256 + y)*256 + xc);
    #pragma unroll
    for (int j = 0; j < 16; j++) {
        int idx = tid + j*256;
        int xx = idx >> 6, ci = idx & 63;
        float v = ts[ci][xx];
        __half hi = __float2half_rn(v);
        __half lo = __float2half_rn(v - __half2float(hi));
        g_cThi[(pxbase + xx)*64 + ci] = hi;
        g_cTlo[(pxbase + xx)*64 + ci] = lo;
    }
}

// ---------------- Kernel A ----------------
__global__ void __launch_bounds__(256) kA(const float* __restrict__ c) {
    __shared__ float tab[8192];
    __shared__ float rows[8][256];
    int tid = threadIdx.x;
    for (int i = tid; i < 8192; i += 256) tab[i] = g_tabA[i];
    __syncthreads();
    int w = tid >> 5, lane = tid & 31;
    int rowBase = blockIdx.x * 128;
    for (int it = 0; it < 16; it++) {
        int row = rowBase + it*8 + w;
        const float* src = c + (size_t)row * 256;
        #pragma unroll
        for (int k = 0; k < 8; k++) rows[w][lane + k*32] = src[lane + k*32];
        __syncwarp();
        float a0 = 0.f, a1 = 0.f, a2 = 0.f, a3 = 0.f;
        #pragma unroll 4
        for (int x = 0; x < 256; x += 4) {
            a0 += rows[w][x+0] * tab[(x+0)*32 + lane];
            a1 += rows[w][x+1] * tab[(x+1)*32 + lane];
            a2 += rows[w][x+2] * tab[(x+2)*32 + lane];
            a3 += rows[w][x+3] * tab[(x+3)*32 + lane];
        }
        g_X1[(size_t)row*32 + lane] = (a0 + a1) + (a2 + a3);
        __syncwarp();
    }
}

// ---------------- Kernel B ----------------
__global__ void __launch_bounds__(512) kB() {
    __shared__ float xs[8192];
    __shared__ float csm[256], ssm[256];
    int tid = threadIdx.x;
    int img = blockIdx.x;
    const float* src = g_X1 + (size_t)img * 8192;
    for (int i = tid; i < 8192; i += 512) xs[i] = src[i];
    if (tid < 256) { csm[tid] = g_cosT[tid]; ssm[tid] = g_sinT[tid]; }
    __syncthreads();
    int kyi = tid >> 4, kx = tid & 15;
    int ky = (kyi < 16) ? kyi : kyi + 224;
    float ar = 0.f, ai = 0.f;
    for (int y = 0; y < 256; y++) {
        int j = (ky * y) & 255;
        float cv = csm[j], sv = ssm[j];
        float2 v = *(const float2*)&xs[y*32 + 2*kx];
        ar += v.x * cv + v.y * sv;
        ai += v.y * cv - v.x * sv;
    }
    *(float2*)&g_CFT[((size_t)img*512 + tid)*2] = make_float2(ar, ai);
}

// ---------------- Kernel C ----------------
__global__ void __launch_bounds__(128) kC(const float* __restrict__ w1r, const float* __restrict__ w1i,
                                          const float* __restrict__ w2r, const float* __restrict__ w2i) {
    __shared__ float wr_s[4096], wi_s[4096], cf_s[2048];
    int tid = threadIdx.x;
    int m = blockIdx.x;
    int kyi = m >> 4, kx = m & 15;
    const float* br; const float* bi; int woff;
    if (kyi < 16) { br = w1r; bi = w1i; woff = kyi*16 + kx; }
    else          { br = w2r; bi = w2i; woff = (kyi-16)*16 + kx; }
    for (int idx = tid; idx < 4096; idx += 128) {
        wr_s[idx] = br[idx*256 + woff];
        wi_s[idx] = bi[idx*256 + woff];
    }
    for (int idx = tid; idx < 1024; idx += 128) {
        float2 v = *(const float2*)&g_CFT[((size_t)idx*512 + m)*2];
        cf_s[2*idx] = v.x; cf_s[2*idx+1] = v.y;
    }
    __syncthreads();
    int o = tid & 63, h = tid >> 6;
    float aR[8], aI[8];
    #pragma unroll
    for (int q = 0; q < 8; q++) { aR[q] = 0.f; aI[q] = 0.f; }
    for (int i = 0; i < 64; i++) {
        float wr = wr_s[i*64 + o], wi = wi_s[i*64 + o];
        #pragma unroll
        for (int q = 0; q < 8; q++) {
            int b = h*8 + q;
            float cr = cf_s[(b*64 + i)*2], ci2 = cf_s[(b*64 + i)*2 + 1];
            aR[q] += cr*wr - ci2*wi;
            aI[q] += cr*wi + ci2*wr;
        }
    }
    #pragma unroll
    for (int q = 0; q < 8; q++) {
        int b = h*8 + q;
        *(float2*)&g_OFT[(((size_t)b*64 + o)*512 + m)*2] = make_float2(aR[q], aI[q]);
    }
}

// ---------------- Kernel D ----------------
__global__ void __launch_bounds__(256) kD() {
    __shared__ float tmp[256*34];
    __shared__ float oft_s[1024];
    __shared__ float csm[256], ssm[256];
    int tid = threadIdx.x;
    int img = blockIdx.x;
    const float* src = g_OFT + (size_t)img * 1024;
    for (int i = tid; i < 1024; i += 256) oft_s[i] = src[i];
    if (tid < 256) { csm[tid] = g_cosT[tid]; ssm[tid] = g_sinT[tid]; }
    __syncthreads();
    {
        int y = tid;
        float aR[16], aI[16];
        #pragma unroll
        for (int k = 0; k < 16; k++) { aR[k] = 0.f; aI[k] = 0.f; }
        for (int kyi = 0; kyi < 32; kyi++) {
            int ky = (kyi < 16) ? kyi : kyi + 224;
            int j = (ky * y) & 255;
            float cv = csm[j], sv = ssm[j];
            const float* ob = &oft_s[kyi*32];
            #pragma unroll
            for (int kx = 0; kx < 16; kx++) {
                float orr = ob[2*kx], oii = ob[2*kx+1];
                aR[kx] += orr*cv - oii*sv;
                aI[kx] += orr*sv + oii*cv;
            }
        }
        #pragma unroll
        for (int kx = 0; kx < 16; kx++) {
            tmp[y*34 + 2*kx]   = aR[kx];
            tmp[y*34 + 2*kx+1] = aI[kx];
        }
    }
    __syncthreads();
    {
        int x = tid;
        float f[32];
        #pragma unroll
        for (int n = 0; n < 32; n++) f[n] = g_tabFT[n*256 + x];
        float* gdst = g_G + (size_t)img * 65536;
        for (int y = 0; y < 256; y++) {
            const float* tr = &tmp[y*34];
            float a0 = 0.f, a1 = 0.f, a2 = 0.f, a3 = 0.f;
            #pragma unroll
            for (int n = 0; n < 32; n += 4) {
                a0 += tr[n+0] * f[n+0];
                a1 += tr[n+1] * f[n+1];
                a2 += tr[n+2] * f[n+2];
                a3 += tr[n+3] * f[n+3];
            }
            gdst[y*256 + x] = (a0 + a1) + (a2 + a3);
        }
    }
}

// ---------------- kE3: mma.sync f16-split conv * G -> out ----------------
// SMEM: [0,256) bias | buf{0,1} @ 1024 + buf*49152:
//       A hi 16K | A lo 16K | W hi 8K | W lo 8K   (48KB per buf)
// total 99328 -> 2 CTAs/SM
#define E3_SM_BUF  1024
#define E3_BUFSZ   49152
#define E3_SMEM    99328
#define E3_NT      4

__device__ __forceinline__ void stageA(uint32_t dst, long long px0, int tap, int tid) {
    int dy = tap / 3, dx = tap - dy * 3;
    long long off = (long long)(dy - 1) * 256 + (dx - 1);
    #pragma unroll
    for (int j = 0; j < 8; j++) {
        int o = tid + j * 128;
        int row = o >> 3, ch = o & 7;
        long long spx = px0 + row + off;
        spx = spx < 0 ? 0 : (spx >= NPX ? (long long)(NPX - 1) : spx);
        uint32_t d = SWZ128((uint32_t)(row * 128 + ch * 16));
        cpasync16(dst + d,         g_cThi + spx * 64 + ch * 8);
        cpasync16(dst + 16384 + d, g_cTlo + spx * 64 + ch * 8);
    }
}
__device__ __forceinline__ void stageW(uint32_t dst, int tap, int tid) {
    const char* src = g_wPk + (size_t)tap * 16384;
    #pragma unroll
    for (int j = 0; j < 4; j++) {
        int o = tid + j * 128;        // 512 x 16B = 8KB... need 16KB -> 8 iters of 16B? 1024*16=16KB
        cpasync16(dst + o * 16,        src + (size_t)o * 16);
        cpasync16(dst + 8192 + o * 16, src + 8192 + (size_t)o * 16);
    }
}

__global__ void __launch_bounds__(128, 2) kE3(const float* __restrict__ bias,
                                              float* __restrict__ out) {
    extern __shared__ char sm[];
    uint32_t smb = smem_u32(sm);
    int tid = threadIdx.x, w = tid >> 5, lane = tid & 31;

    if (tid < 64) ((float*)sm)[tid] = bias[tid];

    // lane constants for ldmatrix addressing
    int arow0 = w * 32 + (lane & 15);              // + mb*16
    int a_uh  = lane >> 4;                         // A 16B-col half
    int wrow  = (lane & 7) + ((lane >> 4) << 3);   // + np*16
    int w_uh  = (lane >> 3) & 1;                   // W 16B-col half
    int erow  = lane >> 2;                         // epilogue row in m16 block
    int ecol  = (lane & 3) * 2;                    // epilogue n within n8 block

    long long px0_base = (long long)blockIdx.x * (E3_NT * 128);

    float acc[2][8][4];

    // prologue: stage t=0 into buf0
    stageA(smb + E3_SM_BUF, px0_base, 0, tid);
    stageW(smb + E3_SM_BUF + 32768, 0, tid);
    CP_COMMIT();

    const int T = E3_NT * 9;
    for (int t = 0; t < T; t++) {
        int tile = t / 9, tap = t - tile * 9;
        int buf = t & 1;
        if (t + 1 < T) {
            int t2 = t + 1, tile2 = t2 / 9, tap2 = t2 - tile2 * 9;
            uint32_t b2 = smb + E3_SM_BUF + (t2 & 1) * E3_BUFSZ;
            stageA(b2, px0_base + (long long)tile2 * 128, tap2, tid);
            stageW(b2 + 32768, tap2, tid);
            CP_COMMIT();
            CP_WAIT1();
        } else {
            CP_WAIT0();
        }
        __syncthreads();

        if (tap == 0) {
            #pragma unroll
            for (int mb = 0; mb < 2; mb++)
                #pragma unroll
                for (int nb = 0; nb < 8; nb++)
                    #pragma unroll
                    for (int q = 0; q < 4; q++) acc[mb][nb][q] = 0.f;
        }

        uint32_t Ab = smb + E3_SM_BUF + buf * E3_BUFSZ;
        uint32_t Wb = Ab + 32768;
        #pragma unroll
        for (int kc = 0; kc < 4; kc++) {
            uint32_t ah[2][4], al[2][4], wf[4][4];
            uint32_t wad[4];
            #pragma unroll
            for (int mb = 0; mb < 2; mb++) {
                int row = arow0 + mb * 16;
                uint32_t ra = Ab + row * 128 + (((kc * 2 + a_uh) ^ (row & 7)) << 4);
                ldsm4(ah[mb], ra);
                ldsm4(al[mb], ra + 16384);
            }
            #pragma unroll
            for (int np = 0; np < 4; np++) {
                int row = np * 16 + wrow;
                wad[np] = Wb + row * 128 + (((kc * 2 + w_uh) ^ (row & 7)) << 4);
                ldsm4(wf[np], wad[np]);            // W hi
            }
            #pragma unroll
            for (int mb = 0; mb < 2; mb++)
                #pragma unroll
                for (int nb = 0; nb < 8; nb++)
                    mma16816(acc[mb][nb], ah[mb], &wf[nb >> 1][(nb & 1) * 2]);
            #pragma unroll
            for (int mb = 0; mb < 2; mb++)
                #pragma unroll
                for (int nb = 0; nb < 8; nb++)
                    mma16816(acc[mb][nb], al[mb], &wf[nb >> 1][(nb & 1) * 2]);
            #pragma unroll
            for (int np = 0; np < 4; np++)
                ldsm4(wf[np], wad[np] + 8192);     // W lo (reuse regs)
            #pragma unroll
            for (int mb = 0; mb < 2; mb++)
                #pragma unroll
                for (int nb = 0; nb < 8; nb++)
                    mma16816(acc[mb][nb], ah[mb], &wf[nb >> 1][(nb & 1) * 2]);
        }
        __syncthreads();

        if (tap == 8) {
            // epilogue: bias + global-branch multiply
            const float* bias_s = (const float*)sm;
            long long pxw = px0_base + (long long)tile * 128 + w * 32 + erow;
            #pragma unroll
            for (int mb = 0; mb < 2; mb++) {
                long long pxA = pxw + mb * 16;
                long long pxB = pxA + 8;
                size_t baseA = ((size_t)(pxA >> 16)) * 64 * 65536 + (size_t)(pxA & 65535);
                size_t baseB = ((size_t)(pxB >> 16)) * 64 * 65536 + (size_t)(pxB & 65535);
                #pragma unroll
                for (int nb = 0; nb < 8; nb++) {
                    int co = nb * 8 + ecol;
                    float b0 = bias_s[co], b1 = bias_s[co + 1];
                    size_t i00 = baseA + (size_t)co * 65536;
                    size_t i01 = i00 + 65536;
                    size_t i10 = baseB + (size_t)co * 65536;
                    size_t i11 = i10 + 65536;
                    out[i00] = (acc[mb][nb][0] + b0) * g_G[i00];
                    out[i01] = (acc[mb][nb][1] + b1) * g_G[i01];
                    out[i10] = (acc[mb][nb][2] + b0) * g_G[i10];
                    out[i11] = (acc[mb][nb][3] + b1) * g_G[i11];
                }
            }
        }
    }
}

// ---------------- kP: exact fp32 patch of wrap-border pixels ----------------
__global__ void __launch_bounds__(256) kP(const float* __restrict__ c,
                                          const float* __restrict__ bias,
                                          float* __restrict__ out) {
    int b = blockIdx.x;
    int s = blockIdx.y;
    int cobase = blockIdx.z * 16;
    int t = threadIdx.x;
    int y, x;
    if (s == 0)      { y = 0;   x = t; }
    else if (s == 1) { y = 255; x = t; }
    else if (s == 2) { y = t;   x = 0; }
    else             { y = t;   x = 255; }

    float acc[16];
    #pragma unroll
    for (int q = 0; q < 16; q++) acc[q] = 0.f;

    const float* cb = c + (size_t)b * 64 * 65536;
    for (int ci = 0; ci < 64; ci++) {
        const float* p = cb + (size_t)ci * 65536;
        float v[9];
        #pragma unroll
        for (int dy = 0; dy < 3; dy++)
            #pragma unroll
            for (int dx = 0; dx < 3; dx++)
                v[dy*3+dx] = p[((y + dy + 255) & 255) * 256 + ((x + dx + 255) & 255)];
        #pragma unroll
        for (int tap = 0; tap < 9; tap++) {
            const float* wrow = g_wT + ci*576 + tap*64 + cobase;
            #pragma unroll
            for (int q = 0; q < 16; q++) acc[q] += v[tap] * __ldg(&wrow[q]);
        }
    }
    size_t base = (size_t)b * 64 * 65536 + (size_t)y * 256 + x;
    #pragma unroll
    for (int q = 0; q < 16; q++) {
        int co = cobase + q;
        size_t idx = base + (size_t)co * 65536;
        out[idx] = (acc[q] + bias[co]) * g_G[idx];
    }
}

// ---------------- launch ----------------
extern "C" void kernel_launch(void* const* d_in, const int* in_sizes, int n_in,
                              void* d_out, int out_size) {
    const float* c      = (const float*)d_in[0];
    const float* w1r    = (const float*)d_in[1];
    const float* w1i    = (const float*)d_in[2];
    const float* w2r    = (const float*)d_in[3];
    const float* w2i    = (const float*)d_in[4];
    const float* conv_w = (const float*)d_in[5];
    const float* conv_b = (const float*)d_in[6];
    float* out = (float*)d_out;

    cudaFuncSetAttribute(kE3, cudaFuncAttributeMaxDynamicSharedMemorySize, E3_SMEM);

    k_init<<<64, 256>>>(conv_w);
    kT<<<dim3(4, 256, 16), 256>>>(c);
    kA<<<2048, 256>>>(c);
    kB<<<1024, 512>>>();
    kC<<<512, 128>>>(w1r, w1i, w2r, w2i);
    kD<<<1024, 256>>>();
    kE3<<<2048, 128, E3_SMEM>>>(conv_b, out);
    kP<<<dim3(16, 4, 4), 256>>>(c, conv_b, out);
}

// round 8
// speedup vs baseline: 1.8417x; 1.3141x over previous
#include <cuda_runtime.h>
#include <cuda_fp16.h>
#include <math.h>
#include <stdint.h>

#define BB   16
#define CH   64
#define HH   256
#define WW   256
#define NIMG (BB*CH)        // 1024
#define NPX  (BB*HH*WW)     // 1048576 flat pixels

// ---------------- scratch (static __device__ allocations only) ----------------
__device__ __align__(16) float g_X1 [NIMG*HH*32];
__device__ __align__(16) float g_CFT[NIMG*512*2];
__device__ __align__(16) float g_OFT[NIMG*512*2];
__device__ __align__(16) float g_G  [NIMG*HH*WW];
__device__ __align__(16) float g_tabA [256*32];
__device__ __align__(16) float g_tabFT[32*256];
__device__ __align__(16) float g_cosT[256];
__device__ __align__(16) float g_sinT[256];
__device__ __align__(16) float g_wT [CH*9*CH];          // [ci][tap][co] (patch kernel)
__device__ __align__(16) __half g_cT [(size_t)NPX*64];  // [px][ci] fp16
__device__ __align__(1024) char g_wPk[9*8192];          // [tap] 64x64 f16 swizzled

// ---------------- helpers ----------------
__device__ __forceinline__ uint32_t smem_u32(const void* p) {
    return (uint32_t)__cvta_generic_to_shared(p);
}
#define SWZ128(bo) ((bo) ^ (((bo) >> 3) & 0x70))

__device__ __forceinline__ void cpasync16(uint32_t saddr, const void* gptr) {
    asm volatile("cp.async.cg.shared.global [%0], [%1], 16;"
                 :: "r"(saddr), "l"(__cvta_generic_to_global(gptr)) : "memory");
}
#define CP_COMMIT()  asm volatile("cp.async.commit_group;" ::: "memory")
#define CP_WAIT0()   asm volatile("cp.async.wait_group 0;" ::: "memory")
#define CP_WAIT1()   asm volatile("cp.async.wait_group 1;" ::: "memory")

__device__ __forceinline__ void ldsm4(uint32_t* r, uint32_t addr) {
    asm volatile("ldmatrix.sync.aligned.m8n8.x4.shared.b16 {%0,%1,%2,%3}, [%4];"
                 : "=r"(r[0]), "=r"(r[1]), "=r"(r[2]), "=r"(r[3]) : "r"(addr));
}
__device__ __forceinline__ void mma16816(float* c, const uint32_t* a, const uint32_t* b) {
    asm volatile(
        "mma.sync.aligned.m16n8k16.row.col.f32.f16.f16.f32 "
        "{%0,%1,%2,%3}, {%4,%5,%6,%7}, {%8,%9}, {%0,%1,%2,%3};"
        : "+f"(c[0]), "+f"(c[1]), "+f"(c[2]), "+f"(c[3])
        : "r"(a[0]), "r"(a[1]), "r"(a[2]), "r"(a[3]), "r"(b[0]), "r"(b[1]));
}

// ---------------- init ----------------
__global__ void k_init(const float* __restrict__ conv_w) {
    const float TWO_PI = 6.28318530717958647692f;
    int tid = blockIdx.x * blockDim.x + threadIdx.x;
    int stride = gridDim.x * blockDim.x;

    if (tid < 256) {
        float ang = TWO_PI * (float)tid / 256.0f;
        g_cosT[tid] = cosf(ang);
        g_sinT[tid] = sinf(ang);
    }
    for (int idx = tid; idx < 256*32; idx += stride) {
        int x = idx >> 5, n = idx & 31, kx = n >> 1;
        float ang = TWO_PI * (float)((kx * x) & 255) / 256.0f;
        g_tabA[idx] = (n & 1) ? -sinf(ang) : cosf(ang);
    }
    for (int idx = tid; idx < 32*256; idx += stride) {
        int n = idx >> 8, x = idx & 255, kx = n >> 1;
        float sc = (kx == 0 ? 1.0f : 2.0f) / 65536.0f;
        float ang = TWO_PI * (float)((kx * x) & 255) / 256.0f;
        g_tabFT[idx] = (n & 1) ? -sc * sinf(ang) : sc * cosf(ang);
    }
    for (int idx = tid; idx < CH*9*CH; idx += stride) {
        int co = idx & 63;
        int rest = idx >> 6;
        int t  = rest % 9;
        int ci = rest / 9;
        g_wT[idx] = conv_w[(co*CH + ci)*9 + t];
    }
    // packed f16 weights [tap][co rows][ci], 128B rows, XOR-swizzled
    for (int idx = tid; idx < 9*4096; idx += stride) {
        int t = idx >> 12;
        int r = idx & 4095;
        int co = r >> 6, ci = r & 63;
        float w = conv_w[(co*CH + ci)*9 + t];
        uint32_t boff = SWZ128((uint32_t)(co*128 + ci*2));
        *(__half*)(g_wPk + (size_t)t*8192 + boff) = __float2half_rn(w);
    }
}

// ---------------- kT: transpose input -> [px][ci] fp16 ----------------
__global__ void __launch_bounds__(256) kT(const float* __restrict__ c) {
    __shared__ float ts[64][65];
    int tid = threadIdx.x;
    int xc = blockIdx.x * 64;
    int y  = blockIdx.y;
    int b  = blockIdx.z;
    #pragma unroll
    for (int j = 0; j < 16; j++) {
        int idx = tid + j*256;
        int ci = idx >> 6, xx = idx & 63;
        ts[ci][xx] = c[((size_t)(b*64 + ci))*65536 + y*256 + xc + xx];
    }
    __syncthreads();
    size_t pxbase = (((size_t)b*256 + y)*256 + xc);
    #pragma unroll
    for (int j = 0; j < 16; j++) {
        int idx = tid + j*256;
        int xx = idx >> 6, ci = idx & 63;
        g_cT[(pxbase + xx)*64 + ci] = __float2half_rn(ts[ci][xx]);
    }
}

// ---------------- Kernel A ----------------
__global__ void __launch_bounds__(256) kA(const float* __restrict__ c) {
    __shared__ float tab[8192];
    __shared__ float rows[8][256];
    int tid = threadIdx.x;
    for (int i = tid; i < 8192; i += 256) tab[i] = g_tabA[i];
    __syncthreads();
    int w = tid >> 5, lane = tid & 31;
    int rowBase = blockIdx.x * 128;
    for (int it = 0; it < 16; it++) {
        int row = rowBase + it*8 + w;
        const float* src = c + (size_t)row * 256;
        #pragma unroll
        for (int k = 0; k < 8; k++) rows[w][lane + k*32] = src[lane + k*32];
        __syncwarp();
        float a0 = 0.f, a1 = 0.f, a2 = 0.f, a3 = 0.f;
        #pragma unroll 4
        for (int x = 0; x < 256; x += 4) {
            a0 += rows[w][x+0] * tab[(x+0)*32 + lane];
            a1 += rows[w][x+1] * tab[(x+1)*32 + lane];
            a2 += rows[w][x+2] * tab[(x+2)*32 + lane];
            a3 += rows[w][x+3] * tab[(x+3)*32 + lane];
        }
        g_X1[(size_t)row*32 + lane] = (a0 + a1) + (a2 + a3);
        __syncwarp();
    }
}

// ---------------- Kernel B ----------------
__global__ void __launch_bounds__(512) kB() {
    __shared__ float xs[8192];
    __shared__ float csm[256], ssm[256];
    int tid = threadIdx.x;
    int img = blockIdx.x;
    const float* src = g_X1 + (size_t)img * 8192;
    for (int i = tid; i < 8192; i += 512) xs[i] = src[i];
    if (tid < 256) { csm[tid] = g_cosT[tid]; ssm[tid] = g_sinT[tid]; }
    __syncthreads();
    int kyi = tid >> 4, kx = tid & 15;
    int ky = (kyi < 16) ? kyi : kyi + 224;
    float ar = 0.f, ai = 0.f;
    for (int y = 0; y < 256; y++) {
        int j = (ky * y) & 255;
        float cv = csm[j], sv = ssm[j];
        float2 v = *(const float2*)&xs[y*32 + 2*kx];
        ar += v.x * cv + v.y * sv;
        ai += v.y * cv - v.x * sv;
    }
    *(float2*)&g_CFT[((size_t)img*512 + tid)*2] = make_float2(ar, ai);
}

// ---------------- Kernel C ----------------
__global__ void __launch_bounds__(128) kC(const float* __restrict__ w1r, const float* __restrict__ w1i,
                                          const float* __restrict__ w2r, const float* __restrict__ w2i) {
    __shared__ float wr_s[4096], wi_s[4096], cf_s[2048];
    int tid = threadIdx.x;
    int m = blockIdx.x;
    int kyi = m >> 4, kx = m & 15;
    const float* br; const float* bi; int woff;
    if (kyi < 16) { br = w1r; bi = w1i; woff = kyi*16 + kx; }
    else          { br = w2r; bi = w2i; woff = (kyi-16)*16 + kx; }
    for (int idx = tid; idx < 4096; idx += 128) {
        wr_s[idx] = br[idx*256 + woff];
        wi_s[idx] = bi[idx*256 + woff];
    }
    for (int idx = tid; idx < 1024; idx += 128) {
        float2 v = *(const float2*)&g_CFT[((size_t)idx*512 + m)*2];
        cf_s[2*idx] = v.x; cf_s[2*idx+1] = v.y;
    }
    __syncthreads();
    int o = tid & 63, h = tid >> 6;
    float aR[8], aI[8];
    #pragma unroll
    for (int q = 0; q < 8; q++) { aR[q] = 0.f; aI[q] = 0.f; }
    for (int i = 0; i < 64; i++) {
        float wr = wr_s[i*64 + o], wi = wi_s[i*64 + o];
        #pragma unroll
        for (int q = 0; q < 8; q++) {
            int b = h*8 + q;
            float cr = cf_s[(b*64 + i)*2], ci2 = cf_s[(b*64 + i)*2 + 1];
            aR[q] += cr*wr - ci2*wi;
            aI[q] += cr*wi + ci2*wr;
        }
    }
    #pragma unroll
    for (int q = 0; q < 8; q++) {
        int b = h*8 + q;
        *(float2*)&g_OFT[(((size_t)b*64 + o)*512 + m)*2] = make_float2(aR[q], aI[q]);
    }
}

// ---------------- Kernel D ----------------
__global__ void __launch_bounds__(256) kD() {
    __shared__ float tmp[256*34];
    __shared__ float oft_s[1024];
    __shared__ float csm[256], ssm[256];
    int tid = threadIdx.x;
    int img = blockIdx.x;
    const float* src = g_OFT + (size_t)img * 1024;
    for (int i = tid; i < 1024; i += 256) oft_s[i] = src[i];
    if (tid < 256) { csm[tid] = g_cosT[tid]; ssm[tid] = g_sinT[tid]; }
    __syncthreads();
    {
        int y = tid;
        float aR[16], aI[16];
        #pragma unroll
        for (int k = 0; k < 16; k++) { aR[k] = 0.f; aI[k] = 0.f; }
        for (int kyi = 0; kyi < 32; kyi++) {
            int ky = (kyi < 16) ? kyi : kyi + 224;
            int j = (ky * y) & 255;
            float cv = csm[j], sv = ssm[j];
            const float* ob = &oft_s[kyi*32];
            #pragma unroll
            for (int kx = 0; kx < 16; kx++) {
                float orr = ob[2*kx], oii = ob[2*kx+1];
                aR[kx] += orr*cv - oii*sv;
                aI[kx] += orr*sv + oii*cv;
            }
        }
        #pragma unroll
        for (int kx = 0; kx < 16; kx++) {
            tmp[y*34 + 2*kx]   = aR[kx];
            tmp[y*34 + 2*kx+1] = aI[kx];
        }
    }
    __syncthreads();
    {
        int x = tid;
        float f[32];
        #pragma unroll
        for (int n = 0; n < 32; n++) f[n] = g_tabFT[n*256 + x];
        float* gdst = g_G + (size_t)img * 65536;
        for (int y = 0; y < 256; y++) {
            const float* tr = &tmp[y*34];
            float a0 = 0.f, a1 = 0.f, a2 = 0.f, a3 = 0.f;
            #pragma unroll
            for (int n = 0; n < 32; n += 4) {
                a0 += tr[n+0] * f[n+0];
                a1 += tr[n+1] * f[n+1];
                a2 += tr[n+2] * f[n+2];
                a3 += tr[n+3] * f[n+3];
            }
            gdst[y*256 + x] = (a0 + a1) + (a2 + a3);
        }
    }
}

// ---------------- kE3: single-pass fp16 mma.sync conv * G -> out ----------------
// SMEM: [0,256) bias | buf{0,1} @ 1024 + buf*24576:  A 16K | W 8K
// total 50176 -> 4 CTAs/SM
#define E3_SM_BUF  1024
#define E3_BUFSZ   24576
#define E3_SMEM    50176
#define E3_NT      4

__device__ __forceinline__ void stageA(uint32_t dst, long long px0, int tap, int tid) {
    int dy = tap / 3, dx = tap - dy * 3;
    long long off = (long long)(dy - 1) * 256 + (dx - 1);
    #pragma unroll
    for (int j = 0; j < 8; j++) {
        int o = tid + j * 128;
        int row = o >> 3, ch = o & 7;
        long long spx = px0 + row + off;
        spx = spx < 0 ? 0 : (spx >= NPX ? (long long)(NPX - 1) : spx);
        uint32_t d = SWZ128((uint32_t)(row * 128 + ch * 16));
        cpasync16(dst + d, g_cT + spx * 64 + ch * 8);
    }
}
__device__ __forceinline__ void stageW(uint32_t dst, int tap, int tid) {
    const char* src = g_wPk + (size_t)tap * 8192;
    #pragma unroll
    for (int j = 0; j < 4; j++) {
        int o = tid + j * 128;
        cpasync16(dst + o * 16, src + (size_t)o * 16);
    }
}

__global__ void __launch_bounds__(128, 4) kE3(const float* __restrict__ bias,
                                              float* __restrict__ out) {
    extern __shared__ char sm[];
    uint32_t smb = smem_u32(sm);
    int tid = threadIdx.x, w = tid >> 5, lane = tid & 31;

    if (tid < 64) ((float*)sm)[tid] = bias[tid];

    // lane constants for ldmatrix addressing
    int arow0 = w * 32 + (lane & 15);              // + mb*16
    int a_uh  = lane >> 4;                         // A 16B-col half
    int wrow  = (lane & 7) + ((lane >> 4) << 3);   // + np*16
    int w_uh  = (lane >> 3) & 1;                   // W 16B-col half
    int erow  = lane >> 2;                         // epilogue row in m16 block
    int ecol  = (lane & 3) * 2;                    // epilogue n within n8 block

    long long px0_base = (long long)blockIdx.x * (E3_NT * 128);

    float acc[2][8][4];

    // prologue: stage t=0 into buf0
    stageA(smb + E3_SM_BUF, px0_base, 0, tid);
    stageW(smb + E3_SM_BUF + 16384, 0, tid);
    CP_COMMIT();

    const int T = E3_NT * 9;
    for (int t = 0; t < T; t++) {
        int tile = t / 9, tap = t - tile * 9;
        int buf = t & 1;
        if (t + 1 < T) {
            int t2 = t + 1, tile2 = t2 / 9, tap2 = t2 - tile2 * 9;
            uint32_t b2 = smb + E3_SM_BUF + (t2 & 1) * E3_BUFSZ;
            stageA(b2, px0_base + (long long)tile2 * 128, tap2, tid);
            stageW(b2 + 16384, tap2, tid);
            CP_COMMIT();
            CP_WAIT1();
        } else {
            CP_WAIT0();
        }
        __syncthreads();

        if (tap == 0) {
            #pragma unroll
            for (int mb = 0; mb < 2; mb++)
                #pragma unroll
                for (int nb = 0; nb < 8; nb++)
                    #pragma unroll
                    for (int q = 0; q < 4; q++) acc[mb][nb][q] = 0.f;
        }

        uint32_t Ab = smb + E3_SM_BUF + buf * E3_BUFSZ;
        uint32_t Wb = Ab + 16384;
        #pragma unroll
        for (int kc = 0; kc < 4; kc++) {
            uint32_t ah[2][4], wf[4][4];
            #pragma unroll
            for (int mb = 0; mb < 2; mb++) {
                int row = arow0 + mb * 16;
                uint32_t ra = Ab + row * 128 + (((kc * 2 + a_uh) ^ (row & 7)) << 4);
                ldsm4(ah[mb], ra);
            }
            #pragma unroll
            for (int np = 0; np < 4; np++) {
                int row = np * 16 + wrow;
                uint32_t rw = Wb + row * 128 + (((kc * 2 + w_uh) ^ (row & 7)) << 4);
                ldsm4(wf[np], rw);
            }
            #pragma unroll
            for (int mb = 0; mb < 2; mb++)
                #pragma unroll
                for (int nb = 0; nb < 8; nb++)
                    mma16816(acc[mb][nb], ah[mb], &wf[nb >> 1][(nb & 1) * 2]);
        }
        __syncthreads();

        if (tap == 8) {
            // epilogue: bias + global-branch multiply
            const float* bias_s = (const float*)sm;
            long long pxw = px0_base + (long long)tile * 128 + w * 32 + erow;
            #pragma unroll
            for (int mb = 0; mb < 2; mb++) {
                long long pxA = pxw + mb * 16;
                long long pxB = pxA + 8;
                size_t baseA = ((size_t)(pxA >> 16)) * 64 * 65536 + (size_t)(pxA & 65535);
                size_t baseB = ((size_t)(pxB >> 16)) * 64 * 65536 + (size_t)(pxB & 65535);
                #pragma unroll
                for (int nb = 0; nb < 8; nb++) {
                    int co = nb * 8 + ecol;
                    float b0 = bias_s[co], b1 = bias_s[co + 1];
                    size_t i00 = baseA + (size_t)co * 65536;
                    size_t i01 = i00 + 65536;
                    size_t i10 = baseB + (size_t)co * 65536;
                    size_t i11 = i10 + 65536;
                    out[i00] = (acc[mb][nb][0] + b0) * g_G[i00];
                    out[i01] = (acc[mb][nb][1] + b1) * g_G[i01];
                    out[i10] = (acc[mb][nb][2] + b0) * g_G[i10];
                    out[i11] = (acc[mb][nb][3] + b1) * g_G[i11];
                }
            }
        }
    }
}

// ---------------- kP: exact fp32 patch of wrap-border pixels ----------------
__global__ void __launch_bounds__(256) kP(const float* __restrict__ c,
                                          const float* __restrict__ bias,
                                          float* __restrict__ out) {
    int b = blockIdx.x;
    int s = blockIdx.y;
    int cobase = blockIdx.z * 16;
    int t = threadIdx.x;
    int y, x;
    if (s == 0)      { y = 0;   x = t; }
    else if (s == 1) { y = 255; x = t; }
    else if (s == 2) { y = t;   x = 0; }
    else             { y = t;   x = 255; }

    float acc[16];
    #pragma unroll
    for (int q = 0; q < 16; q++) acc[q] = 0.f;

    const float* cb = c + (size_t)b * 64 * 65536;
    for (int ci = 0; ci < 64; ci++) {
        const float* p = cb + (size_t)ci * 65536;
        float v[9];
        #pragma unroll
        for (int dy = 0; dy < 3; dy++)
            #pragma unroll
            for (int dx = 0; dx < 3; dx++)
                v[dy*3+dx] = p[((y + dy + 255) & 255) * 256 + ((x + dx + 255) & 255)];
        #pragma unroll
        for (int tap = 0; tap < 9; tap++) {
            const float* wrow = g_wT + ci*576 + tap*64 + cobase;
            #pragma unroll
            for (int q = 0; q < 16; q++) acc[q] += v[tap] * __ldg(&wrow[q]);
        }
    }
    size_t base = (size_t)b * 64 * 65536 + (size_t)y * 256 + x;
    #pragma unroll
    for (int q = 0; q < 16; q++) {
        int co = cobase + q;
        size_t idx = base + (size_t)co * 65536;
        out[idx] = (acc[q] + bias[co]) * g_G[idx];
    }
}

// ---------------- launch ----------------
extern "C" void kernel_launch(void* const* d_in, const int* in_sizes, int n_in,
                              void* d_out, int out_size) {
    const float* c      = (const float*)d_in[0];
    const float* w1r    = (const float*)d_in[1];
    const float* w1i    = (const float*)d_in[2];
    const float* w2r    = (const float*)d_in[3];
    const float* w2i    = (const float*)d_in[4];
    const float* conv_w = (const float*)d_in[5];
    const float* conv_b = (const float*)d_in[6];
    float* out = (float*)d_out;

    cudaFuncSetAttribute(kE3, cudaFuncAttributeMaxDynamicSharedMemorySize, E3_SMEM);

    k_init<<<64, 256>>>(conv_w);
    kT<<<dim3(4, 256, 16), 256>>>(c);
    kA<<<2048, 256>>>(c);
    kB<<<1024, 512>>>();
    kC<<<512, 128>>>(w1r, w1i, w2r, w2i);
    kD<<<1024, 256>>>();
    kE3<<<2048, 128, E3_SMEM>>>(conv_b, out);
    kP<<<dim3(16, 4, 4), 256>>>(c, conv_b, out);
}

// round 9
// speedup vs baseline: 1.9464x; 1.0569x over previous
#include <cuda_runtime.h>
#include <cuda_fp16.h>
#include <math.h>
#include <stdint.h>

#define BB   16
#define CH   64
#define HH   256
#define WW   256
#define NIMG (BB*CH)        // 1024
#define NPX  (BB*HH*WW)     // 1048576 flat pixels

// ---------------- scratch (static __device__ allocations only) ----------------
__device__ __align__(16) float g_X1 [NIMG*HH*32];
__device__ __align__(16) float g_CFT[NIMG*512*2];
__device__ __align__(16) float g_OFT[NIMG*512*2];
__device__ __align__(16) float g_G  [NIMG*HH*WW];
__device__ __align__(16) float g_tabA [256*32];
__device__ __align__(16) float g_tabFT[32*256];
__device__ __align__(16) float g_cosT[256];
__device__ __align__(16) float g_sinT[256];
__device__ __align__(16) float g_wT [CH*9*CH];          // [ci][tap][co] (patch kernel)
__device__ __align__(16) __half g_cT [(size_t)NPX*64];  // [px][ci] fp16
__device__ __align__(1024) char g_wPk[9*8192];          // [tap] 64x64 f16 swizzled

// ---------------- helpers ----------------
__device__ __forceinline__ uint32_t smem_u32(const void* p) {
    return (uint32_t)__cvta_generic_to_shared(p);
}
#define SWZ128(bo) ((bo) ^ (((bo) >> 3) & 0x70))

__device__ __forceinline__ unsigned long long packf2(float lo, float hi) {
    unsigned long long d;
    asm("mov.b64 %0, {%1, %2};" : "=l"(d) : "f"(lo), "f"(hi));
    return d;
}
__device__ __forceinline__ unsigned long long fma2(unsigned long long a,
                                                   unsigned long long b,
                                                   unsigned long long c) {
    unsigned long long d;
    asm("fma.rn.f32x2 %0, %1, %2, %3;" : "=l"(d) : "l"(a), "l"(b), "l"(c));
    return d;
}
__device__ __forceinline__ void unpack2(unsigned long long v, float& lo, float& hi) {
    asm("mov.b64 {%0,%1}, %2;" : "=f"(lo), "=f"(hi) : "l"(v));
}

__device__ __forceinline__ void cpasync16(uint32_t saddr, const void* gptr) {
    asm volatile("cp.async.cg.shared.global [%0], [%1], 16;"
                 :: "r"(saddr), "l"(__cvta_generic_to_global(gptr)) : "memory");
}
#define CP_COMMIT()  asm volatile("cp.async.commit_group;" ::: "memory")
#define CP_WAIT0()   asm volatile("cp.async.wait_group 0;" ::: "memory")
#define CP_WAIT1()   asm volatile("cp.async.wait_group 1;" ::: "memory")

__device__ __forceinline__ void ldsm4(uint32_t* r, uint32_t addr) {
    asm volatile("ldmatrix.sync.aligned.m8n8.x4.shared.b16 {%0,%1,%2,%3}, [%4];"
                 : "=r"(r[0]), "=r"(r[1]), "=r"(r[2]), "=r"(r[3]) : "r"(addr));
}
__device__ __forceinline__ void mma16816(float* c, const uint32_t* a, const uint32_t* b) {
    asm volatile(
        "mma.sync.aligned.m16n8k16.row.col.f32.f16.f16.f32 "
        "{%0,%1,%2,%3}, {%4,%5,%6,%7}, {%8,%9}, {%0,%1,%2,%3};"
        : "+f"(c[0]), "+f"(c[1]), "+f"(c[2]), "+f"(c[3])
        : "r"(a[0]), "r"(a[1]), "r"(a[2]), "r"(a[3]), "r"(b[0]), "r"(b[1]));
}

// ---------------- init ----------------
__global__ void k_init(const float* __restrict__ conv_w) {
    const float TWO_PI = 6.28318530717958647692f;
    int tid = blockIdx.x * blockDim.x + threadIdx.x;
    int stride = gridDim.x * blockDim.x;

    if (tid < 256) {
        float ang = TWO_PI * (float)tid / 256.0f;
        g_cosT[tid] = cosf(ang);
        g_sinT[tid] = sinf(ang);
    }
    for (int idx = tid; idx < 256*32; idx += stride) {
        int x = idx >> 5, n = idx & 31, kx = n >> 1;
        float ang = TWO_PI * (float)((kx * x) & 255) / 256.0f;
        g_tabA[idx] = (n & 1) ? -sinf(ang) : cosf(ang);
    }
    for (int idx = tid; idx < 32*256; idx += stride) {
        int n = idx >> 8, x = idx & 255, kx = n >> 1;
        float sc = (kx == 0 ? 1.0f : 2.0f) / 65536.0f;
        float ang = TWO_PI * (float)((kx * x) & 255) / 256.0f;
        g_tabFT[idx] = (n & 1) ? -sc * sinf(ang) : sc * cosf(ang);
    }
    for (int idx = tid; idx < CH*9*CH; idx += stride) {
        int co = idx & 63;
        int rest = idx >> 6;
        int t  = rest % 9;
        int ci = rest / 9;
        g_wT[idx] = conv_w[(co*CH + ci)*9 + t];
    }
    // packed f16 weights [tap][co rows][ci], 128B rows, XOR-swizzled
    for (int idx = tid; idx < 9*4096; idx += stride) {
        int t = idx >> 12;
        int r = idx & 4095;
        int co = r >> 6, ci = r & 63;
        float w = conv_w[(co*CH + ci)*9 + t];
        uint32_t boff = SWZ128((uint32_t)(co*128 + ci*2));
        *(__half*)(g_wPk + (size_t)t*8192 + boff) = __float2half_rn(w);
    }
}

// ---------------- kT: transpose input -> [px][ci] fp16 ----------------
__global__ void __launch_bounds__(256) kT(const float* __restrict__ c) {
    __shared__ float ts[64][65];
    int tid = threadIdx.x;
    int xc = blockIdx.x * 64;
    int y  = blockIdx.y;
    int b  = blockIdx.z;
    #pragma unroll
    for (int j = 0; j < 16; j++) {
        int idx = tid + j*256;
        int ci = idx >> 6, xx = idx & 63;
        ts[ci][xx] = c[((size_t)(b*64 + ci))*65536 + y*256 + xc + xx];
    }
    __syncthreads();
    size_t pxbase = (((size_t)b*256 + y)*256 + xc);
    #pragma unroll
    for (int j = 0; j < 16; j++) {
        int idx = tid + j*256;
        int xx = idx >> 6, ci = idx & 63;
        g_cT[(pxbase + xx)*64 + ci] = __float2half_rn(ts[ci][xx]);
    }
}

// ---------------- Kernel A ----------------
__global__ void __launch_bounds__(256) kA(const float* __restrict__ c) {
    __shared__ float tab[8192];
    __shared__ float rows[8][256];
    int tid = threadIdx.x;
    for (int i = tid; i < 8192; i += 256) tab[i] = g_tabA[i];
    __syncthreads();
    int w = tid >> 5, lane = tid & 31;
    int rowBase = blockIdx.x * 128;
    for (int it = 0; it < 16; it++) {
        int row = rowBase + it*8 + w;
        const float* src = c + (size_t)row * 256;
        #pragma unroll
        for (int k = 0; k < 8; k++) rows[w][lane + k*32] = src[lane + k*32];
        __syncwarp();
        float a0 = 0.f, a1 = 0.f, a2 = 0.f, a3 = 0.f;
        #pragma unroll 4
        for (int x = 0; x < 256; x += 4) {
            a0 += rows[w][x+0] * tab[(x+0)*32 + lane];
            a1 += rows[w][x+1] * tab[(x+1)*32 + lane];
            a2 += rows[w][x+2] * tab[(x+2)*32 + lane];
            a3 += rows[w][x+3] * tab[(x+3)*32 + lane];
        }
        g_X1[(size_t)row*32 + lane] = (a0 + a1) + (a2 + a3);
        __syncwarp();
    }
}

// ---------------- Kernel B ----------------
__global__ void __launch_bounds__(512) kB() {
    __shared__ float xs[8192];
    __shared__ float csm[256], ssm[256];
    int tid = threadIdx.x;
    int img = blockIdx.x;
    const float* src = g_X1 + (size_t)img * 8192;
    for (int i = tid; i < 8192; i += 512) xs[i] = src[i];
    if (tid < 256) { csm[tid] = g_cosT[tid]; ssm[tid] = g_sinT[tid]; }
    __syncthreads();
    int kyi = tid >> 4, kx = tid & 15;
    int ky = (kyi < 16) ? kyi : kyi + 224;
    float ar = 0.f, ai = 0.f;
    for (int y = 0; y < 256; y++) {
        int j = (ky * y) & 255;
        float cv = csm[j], sv = ssm[j];
        float2 v = *(const float2*)&xs[y*32 + 2*kx];
        ar += v.x * cv + v.y * sv;
        ai += v.y * cv - v.x * sv;
    }
    *(float2*)&g_CFT[((size_t)img*512 + tid)*2] = make_float2(ar, ai);
}

// ---------------- Kernel C ----------------
__global__ void __launch_bounds__(128) kC(const float* __restrict__ w1r, const float* __restrict__ w1i,
                                          const float* __restrict__ w2r, const float* __restrict__ w2i) {
    __shared__ float wr_s[4096], wi_s[4096], cf_s[2048];
    int tid = threadIdx.x;
    int m = blockIdx.x;
    int kyi = m >> 4, kx = m & 15;
    const float* br; const float* bi; int woff;
    if (kyi < 16) { br = w1r; bi = w1i; woff = kyi*16 + kx; }
    else          { br = w2r; bi = w2i; woff = (kyi-16)*16 + kx; }
    for (int idx = tid; idx < 4096; idx += 128) {
        wr_s[idx] = br[idx*256 + woff];
        wi_s[idx] = bi[idx*256 + woff];
    }
    for (int idx = tid; idx < 1024; idx += 128) {
        float2 v = *(const float2*)&g_CFT[((size_t)idx*512 + m)*2];
        cf_s[2*idx] = v.x; cf_s[2*idx+1] = v.y;
    }
    __syncthreads();
    int o = tid & 63, h = tid >> 6;
    float aR[8], aI[8];
    #pragma unroll
    for (int q = 0; q < 8; q++) { aR[q] = 0.f; aI[q] = 0.f; }
    for (int i = 0; i < 64; i++) {
        float wr = wr_s[i*64 + o], wi = wi_s[i*64 + o];
        #pragma unroll
        for (int q = 0; q < 8; q++) {
            int b = h*8 + q;
            float cr = cf_s[(b*64 + i)*2], ci2 = cf_s[(b*64 + i)*2 + 1];
            aR[q] += cr*wr - ci2*wi;
            aI[q] += cr*wi + ci2*wr;
        }
    }
    #pragma unroll
    for (int q = 0; q < 8; q++) {
        int b = h*8 + q;
        *(float2*)&g_OFT[(((size_t)b*64 + o)*512 + m)*2] = make_float2(aR[q], aI[q]);
    }
}

// ---------------- Kernel D ----------------
__global__ void __launch_bounds__(256) kD() {
    __shared__ float tmp[256*34];                     // 136B rows, 8B-aligned pairs
    __shared__ float oft_s[1024];
    __shared__ float csm[256], ssm[256];
    int tid = threadIdx.x;
    int img = blockIdx.x;
    const float* src = g_OFT + (size_t)img * 1024;
    for (int i = tid; i < 1024; i += 256) oft_s[i] = src[i];
    if (tid < 256) { csm[tid] = g_cosT[tid]; ssm[tid] = g_sinT[tid]; }
    __syncthreads();
    {   // phase 2: y-iDFT, thread = y
        int y = tid;
        float aR[16], aI[16];
        #pragma unroll
        for (int k = 0; k < 16; k++) { aR[k] = 0.f; aI[k] = 0.f; }
        for (int kyi = 0; kyi < 32; kyi++) {
            int ky = (kyi < 16) ? kyi : kyi + 224;
            int j = (ky * y) & 255;
            float cv = csm[j], sv = ssm[j];
            const float* ob = &oft_s[kyi*32];
            #pragma unroll
            for (int kx = 0; kx < 16; kx++) {
                float orr = ob[2*kx], oii = ob[2*kx+1];
                aR[kx] += orr*cv - oii*sv;
                aI[kx] += orr*sv + oii*cv;
            }
        }
        #pragma unroll
        for (int kx = 0; kx < 16; kx++) {
            tmp[y*34 + 2*kx]   = aR[kx];
            tmp[y*34 + 2*kx+1] = aI[kx];
        }
    }
    __syncthreads();
    {   // phase 3: x synthesis with f32x2, thread = x (column)
        int x = tid;
        unsigned long long f2[16];
        #pragma unroll
        for (int n2 = 0; n2 < 16; n2++)
            f2[n2] = packf2(g_tabFT[(2*n2)*256 + x], g_tabFT[(2*n2+1)*256 + x]);
        float* gdst = g_G + (size_t)img * 65536;
        for (int y = 0; y < 256; y++) {
            const unsigned long long* tr = (const unsigned long long*)&tmp[y*34];
            unsigned long long a0 = 0ULL, a1 = 0ULL, a2 = 0ULL, a3 = 0ULL;
            #pragma unroll
            for (int n2 = 0; n2 < 16; n2 += 4) {
                a0 = fma2(tr[n2+0], f2[n2+0], a0);
                a1 = fma2(tr[n2+1], f2[n2+1], a1);
                a2 = fma2(tr[n2+2], f2[n2+2], a2);
                a3 = fma2(tr[n2+3], f2[n2+3], a3);
            }
            float s0,s1,s2,s3,s4,s5,s6,s7;
            unpack2(a0, s0, s1); unpack2(a1, s2, s3);
            unpack2(a2, s4, s5); unpack2(a3, s6, s7);
            gdst[y*256 + x] = ((s0+s1)+(s2+s3)) + ((s4+s5)+(s6+s7));
        }
    }
}

// ---------------- kE3: single-pass fp16 mma.sync conv * G -> out ----------------
// SMEM: [0,256) bias | buf{0,1} @ 1024 + buf*24576:  A 16K | W 8K
// total 50176 -> 4 CTAs/SM.  NT=2 -> grid 4096 -> 6.9 waves (balanced).
#define E3_SM_BUF  1024
#define E3_BUFSZ   24576
#define E3_SMEM    50176
#define E3_NT      2

__device__ __forceinline__ void stageA(uint32_t dst, long long px0, int tap, int tid) {
    int dy = tap / 3, dx = tap - dy * 3;
    long long off = (long long)(dy - 1) * 256 + (dx - 1);
    #pragma unroll
    for (int j = 0; j < 8; j++) {
        int o = tid + j * 128;
        int row = o >> 3, ch = o & 7;
        long long spx = px0 + row + off;
        spx = spx < 0 ? 0 : (spx >= NPX ? (long long)(NPX - 1) : spx);
        uint32_t d = SWZ128((uint32_t)(row * 128 + ch * 16));
        cpasync16(dst + d, g_cT + spx * 64 + ch * 8);
    }
}
__device__ __forceinline__ void stageW(uint32_t dst, int tap, int tid) {
    const char* src = g_wPk + (size_t)tap * 8192;
    #pragma unroll
    for (int j = 0; j < 4; j++) {
        int o = tid + j * 128;
        cpasync16(dst + o * 16, src + (size_t)o * 16);
    }
}

__global__ void __launch_bounds__(128, 4) kE3(const float* __restrict__ bias,
                                              float* __restrict__ out) {
    extern __shared__ char sm[];
    uint32_t smb = smem_u32(sm);
    int tid = threadIdx.x, w = tid >> 5, lane = tid & 31;

    if (tid < 64) ((float*)sm)[tid] = bias[tid];

    // lane constants for ldmatrix addressing
    int arow0 = w * 32 + (lane & 15);              // + mb*16
    int a_uh  = lane >> 4;                         // A 16B-col half
    int wrow  = (lane & 7) + ((lane >> 4) << 3);   // + np*16
    int w_uh  = (lane >> 3) & 1;                   // W 16B-col half
    int erow  = lane >> 2;                         // epilogue row in m16 block
    int ecol  = (lane & 3) * 2;                    // epilogue n within n8 block

    long long px0_base = (long long)blockIdx.x * (E3_NT * 128);

    float acc[2][8][4];

    // prologue: stage t=0 into buf0
    stageA(smb + E3_SM_BUF, px0_base, 0, tid);
    stageW(smb + E3_SM_BUF + 16384, 0, tid);
    CP_COMMIT();

    const int T = E3_NT * 9;
    for (int t = 0; t < T; t++) {
        int tile = t / 9, tap = t - tile * 9;
        int buf = t & 1;
        if (t + 1 < T) {
            int t2 = t + 1, tile2 = t2 / 9, tap2 = t2 - tile2 * 9;
            uint32_t b2 = smb + E3_SM_BUF + (t2 & 1) * E3_BUFSZ;
            stageA(b2, px0_base + (long long)tile2 * 128, tap2, tid);
            stageW(b2 + 16384, tap2, tid);
            CP_COMMIT();
            CP_WAIT1();
        } else {
            CP_WAIT0();
        }
        __syncthreads();

        if (tap == 0) {
            #pragma unroll
            for (int mb = 0; mb < 2; mb++)
                #pragma unroll
                for (int nb = 0; nb < 8; nb++)
                    #pragma unroll
                    for (int q = 0; q < 4; q++) acc[mb][nb][q] = 0.f;
        }

        uint32_t Ab = smb + E3_SM_BUF + buf * E3_BUFSZ;
        uint32_t Wb = Ab + 16384;
        #pragma unroll
        for (int kc = 0; kc < 4; kc++) {
            uint32_t ah[2][4], wf[4][4];
            #pragma unroll
            for (int mb = 0; mb < 2; mb++) {
                int row = arow0 + mb * 16;
                uint32_t ra = Ab + row * 128 + (((kc * 2 + a_uh) ^ (row & 7)) << 4);
                ldsm4(ah[mb], ra);
            }
            #pragma unroll
            for (int np = 0; np < 4; np++) {
                int row = np * 16 + wrow;
                uint32_t rw = Wb + row * 128 + (((kc * 2 + w_uh) ^ (row & 7)) << 4);
                ldsm4(wf[np], rw);
            }
            #pragma unroll
            for (int mb = 0; mb < 2; mb++)
                #pragma unroll
                for (int nb = 0; nb < 8; nb++)
                    mma16816(acc[mb][nb], ah[mb], &wf[nb >> 1][(nb & 1) * 2]);
        }
        __syncthreads();

        if (tap == 8) {
            // epilogue: bias + global-branch multiply
            const float* bias_s = (const float*)sm;
            long long pxw = px0_base + (long long)tile * 128 + w * 32 + erow;
            #pragma unroll
            for (int mb = 0; mb < 2; mb++) {
                long long pxA = pxw + mb * 16;
                long long pxB = pxA + 8;
                size_t baseA = ((size_t)(pxA >> 16)) * 64 * 65536 + (size_t)(pxA & 65535);
                size_t baseB = ((size_t)(pxB >> 16)) * 64 * 65536 + (size_t)(pxB & 65535);
                #pragma unroll
                for (int nb = 0; nb < 8; nb++) {
                    int co = nb * 8 + ecol;
                    float b0 = bias_s[co], b1 = bias_s[co + 1];
                    size_t i00 = baseA + (size_t)co * 65536;
                    size_t i01 = i00 + 65536;
                    size_t i10 = baseB + (size_t)co * 65536;
                    size_t i11 = i10 + 65536;
                    out[i00] = (acc[mb][nb][0] + b0) * g_G[i00];
                    out[i01] = (acc[mb][nb][1] + b1) * g_G[i01];
                    out[i10] = (acc[mb][nb][2] + b0) * g_G[i10];
                    out[i11] = (acc[mb][nb][3] + b1) * g_G[i11];
                }
            }
        }
    }
}

// ---------------- kP: exact fp32 patch of wrap-border pixels ----------------
__global__ void __launch_bounds__(256) kP(const float* __restrict__ c,
                                          const float* __restrict__ bias,
                                          float* __restrict__ out) {
    int b = blockIdx.x;
    int s = blockIdx.y;
    int cobase = blockIdx.z * 16;
    int t = threadIdx.x;
    int y, x;
    if (s == 0)      { y = 0;   x = t; }
    else if (s == 1) { y = 255; x = t; }
    else if (s == 2) { y = t;   x = 0; }
    else             { y = t;   x = 255; }

    float acc[16];
    #pragma unroll
    for (int q = 0; q < 16; q++) acc[q] = 0.f;

    const float* cb = c + (size_t)b * 64 * 65536;
    for (int ci = 0; ci < 64; ci++) {
        const float* p = cb + (size_t)ci * 65536;
        float v[9];
        #pragma unroll
        for (int dy = 0; dy < 3; dy++)
            #pragma unroll
            for (int dx = 0; dx < 3; dx++)
                v[dy*3+dx] = p[((y + dy + 255) & 255) * 256 + ((x + dx + 255) & 255)];
        #pragma unroll
        for (int tap = 0; tap < 9; tap++) {
            const float* wrow = g_wT + ci*576 + tap*64 + cobase;
            #pragma unroll
            for (int q = 0; q < 16; q++) acc[q] += v[tap] * __ldg(&wrow[q]);
        }
    }
    size_t base = (size_t)b * 64 * 65536 + (size_t)y * 256 + x;
    #pragma unroll
    for (int q = 0; q < 16; q++) {
        int co = cobase + q;
        size_t idx = base + (size_t)co * 65536;
        out[idx] = (acc[q] + bias[co]) * g_G[idx];
    }
}

// ---------------- launch ----------------
extern "C" void kernel_launch(void* const* d_in, const int* in_sizes, int n_in,
                              void* d_out, int out_size) {
    const float* c      = (const float*)d_in[0];
    const float* w1r    = (const float*)d_in[1];
    const float* w1i    = (const float*)d_in[2];
    const float* w2r    = (const float*)d_in[3];
    const float* w2i    = (const float*)d_in[4];
    const float* conv_w = (const float*)d_in[5];
    const float* conv_b = (const float*)d_in[6];
    float* out = (float*)d_out;

    cudaFuncSetAttribute(kE3, cudaFuncAttributeMaxDynamicSharedMemorySize, E3_SMEM);

    k_init<<<64, 256>>>(conv_w);
    kT<<<dim3(4, 256, 16), 256>>>(c);
    kA<<<2048, 256>>>(c);
    kB<<<1024, 512>>>();
    kC<<<512, 128>>>(w1r, w1i, w2r, w2i);
    kD<<<1024, 256>>>();
    kE3<<<4096, 128, E3_SMEM>>>(conv_b, out);
    kP<<<dim3(16, 4, 4), 256>>>(c, conv_b, out);
}